// round 9
// baseline (speedup 1.0000x reference)
#include <cuda_runtime.h>
#include <cuda_fp16.h>

typedef unsigned long long ull;

#define PW    768      // padded width/height
#define PAD   128      // border
#define IMGW  512
#define MAGIC 8388608.0f      // 2^23
#define MAGICH 8388607.5f     // 2^23 - 0.5

// fp16 differential quad images, 4x4 BLOCK-TILED:
//   element E(r,c) = (r>>2)*(PW*4) + (c<<2) + (r&3)
//   -> one 128B cache line = 4 cols x 4 rows of 8B texels.
// Texel = (v00, dx | dy, dxy); bilinear: val = (v00 + wr*dy) + wc*(dx + wr*dxy)
// A (normal):     rows = image y, cols = image x (padded space)
// B (transposed): rows = image x, cols = image y
__device__ ull g_quadA[PW * PW];
__device__ ull g_quadB[PW * PW];

__device__ __forceinline__ int tile_idx(int r, int c) {
    return (r >> 2) * (PW * 4) + (c << 2) + (r & 3);
}

// ---------------- packed f32x2 helpers ----------------
__device__ __forceinline__ ull f2u(float a, float b) {
    ull r; asm("mov.b64 %0, {%1, %2};" : "=l"(r) : "f"(a), "f"(b)); return r;
}
__device__ __forceinline__ void u2f(ull v, float& a, float& b) {
    asm("mov.b64 {%0, %1}, %2;" : "=f"(a), "=f"(b) : "l"(v));
}
__device__ __forceinline__ ull fma2(ull a, ull b, ull c) {
    ull d; asm("fma.rn.f32x2 %0, %1, %2, %3;" : "=l"(d) : "l"(a), "l"(b), "l"(c)); return d;
}
__device__ __forceinline__ ull add2(ull a, ull b) {
    ull d; asm("add.rn.f32x2 %0, %1, %2;" : "=l"(d) : "l"(a), "l"(b)); return d;
}
__device__ __forceinline__ ull packq(float v00, float v01, float v10, float v11) {
    float dx  = v01 - v00;
    float dy  = v10 - v00;
    float dxy = (v11 - v10) - (v01 - v00);
    __half2 lo = __floats2half2_rn(v00, dx);
    __half2 hi = __floats2half2_rn(dy, dxy);
    unsigned a = *reinterpret_cast<unsigned*>(&lo);
    unsigned b = *reinterpret_cast<unsigned*>(&hi);
    return (ull)a | ((ull)b << 32);
}

__device__ __forceinline__ float ipad(const float* img, int v, int u) {
    int sv = v - PAD, su = u - PAD;
    if (sv < 0 || sv >= IMGW || su < 0 || su >= IMGW) return 0.0f;
    return __ldg(&img[sv * IMGW + su]);
}

// ---------------- fused prep: both differential quad images (tiled) ----------------
__global__ void prep_kernel(const float* __restrict__ img) {
    __shared__ float S[33][34];            // S[j][i] = Ip(r0+j, c0+i)
    const int r0 = blockIdx.x * 32;
    const int c0 = blockIdx.y * 32;
    const int tx = threadIdx.x;            // 0..31
    const int ty = threadIdx.y;            // 0..7

    for (int j = ty; j < 33; j += 8)
        for (int i = tx; i < 33; i += 32)
            S[j][i] = ipad(img, r0 + j, c0 + i);
    __syncthreads();

    for (int j = ty; j < 32; j += 8) {
        // QA rows = image y
        g_quadA[tile_idx(r0 + j, c0 + tx)] =
            packq(S[j][tx], S[j][tx + 1], S[j + 1][tx], S[j + 1][tx + 1]);
        // QB rows = image x (transposed)
        g_quadB[tile_idx(c0 + j, r0 + tx)] =
            packq(S[tx][j], S[tx + 1][j], S[tx][j + 1], S[tx + 1][j + 1]);
    }
}

// ---------------- main radon kernel ----------------
// Warp = 8 detectors x 4 y-lanes. Thread: 2 streams x 64 samples, y = yi + 4*t + 256*k.
// 2 streams (vs 4) cuts register state -> 14 resident blocks (56 warps/SM).
__global__ void __launch_bounds__(128, 14) radon_kernel(const float* __restrict__ angles,
                                                        float* __restrict__ out) {
    const int lane = threadIdx.x & 31;
    const int warp = threadIdx.x >> 5;
    const int xi   = lane & 7;
    const int yi   = lane >> 3;
    const int x    = blockIdx.x * 32 + warp * 8 + xi;
    const int a    = blockIdx.y;

    float s, c;
    sincosf(__ldg(&angles[a]), &s, &c);

    const float bx = fmaf((float)x, 2.0f / 512.0f, 1.0f / 512.0f - 1.0f);
    const float Cx = fmaf(256.0f * c, bx, 383.5f - 255.5f * s);
    const float Cy = fmaf(-256.0f * s, bx, 383.5f - 255.5f * c);

    // layout selection
    const bool  tr   = fabsf(s) > fabsf(c);
    const float dcol = tr ? c : s;
    const float drow = tr ? s : c;
    const float Ca   = tr ? Cy : Cx;
    const float Cb   = tr ? Cx : Cy;

    // Biased magic-int addressing (R7-proven):
    //   byte offset = r*8 + c*32 + (r>>2)*24544   (tiled identity)
    //   Ri = B + r, Ci = B + c, B = 0x4B000000 (B%4==0)
    //   lo = Ri*8 + Ci*32 in wrapping u32: true 40B + r*8 + c*32 wraps by 11*2^32,
    //   so fold (B>>2)*24544 + (40B mod 2^32) into basep.
    const char* basep = (const char*)(tr ? g_quadB : g_quadA)
                      - (ull)(0x4B000000u >> 2) * 24544ull
                      - ((0x4B000000ull * 40ull) & 0xFFFFFFFFull);

    const ull S4    = f2u(4.0f * dcol, 4.0f * drow);
    const ull NEG1  = f2u(-1.0f, -1.0f);
    const ull ONE2  = f2u(1.0f, 1.0f);
    const ull MAGH2 = f2u(MAGICH, MAGICH);    // rn(P + (2^23-0.5)) = MAGIC + floor(P)
    const ull NMAG2 = f2u(-MAGIC, -MAGIC);

    const float y0 = (float)yi;
    ull C0 = f2u(fmaf(y0 +   0.0f, dcol, Ca), fmaf(y0 +   0.0f, drow, Cb));
    ull C1 = f2u(fmaf(y0 + 256.0f, dcol, Ca), fmaf(y0 + 256.0f, drow, Cb));

    float acc0 = 0.0f, acc1 = 0.0f;

    ull t2 = f2u(0.0f, 0.0f);

    #pragma unroll 4
    for (int i = 0; i < 64; i++) {
        #pragma unroll
        for (int k = 0; k < 2; k++) {
            const ull Ck = (k == 0) ? C0 : C1;
            float& acc   = (k == 0) ? acc0 : acc1;

            // packed coords (col, row), exact from base (no drift)
            ull p = fma2(t2, S4, Ck);
            ull t = add2(p, MAGH2);            // MAGIC + floor(col|row)
            ull f = add2(t, NMAG2);            // exact floors as floats
            ull w = fma2(f, NEG1, p);          // fractional weights (wc, wr)

            float tcf, trf; u2f(t, tcf, trf);
            int Ci = __float_as_int(tcf);
            int Ri = __float_as_int(trf);
            unsigned lo = (unsigned)Ri * 8u + (unsigned)Ci * 32u;   // wrapping, fold in basep
            const char* ap = basep + (long long)(Ri >> 2) * 24544 + lo;

            uint2 q = __ldg(reinterpret_cast<const uint2*>(ap));
            __half2 A = *reinterpret_cast<__half2*>(&q.x);   // (v00, dx)
            __half2 B = *reinterpret_cast<__half2*>(&q.y);   // (dy, dxy)

            float wc, wr; u2f(w, wc, wr);
            unsigned wr2u;
            asm("cvt.rn.f16x2.f32 %0, %1, %2;" : "=r"(wr2u) : "f"(wr), "f"(wr));
            __half2 wr2 = *reinterpret_cast<__half2*>(&wr2u);

            __half2 mh = __hfma2(wr2, B, A);                 // (m0, md)
            float m0 = __low2float(mh), md = __high2float(mh);

            acc += m0;
            acc = fmaf(wc, md, acc);
        }
        t2 = add2(t2, ONE2);
    }

    float v = acc0 + acc1;
    v += __shfl_xor_sync(0xFFFFFFFFu, v, 8);
    v += __shfl_xor_sync(0xFFFFFFFFu, v, 16);
    if (yi == 0)
        out[a * IMGW + x] = v;
}

extern "C" void kernel_launch(void* const* d_in, const int* in_sizes, int n_in,
                              void* d_out, int out_size) {
    const float* data   = (const float*)d_in[0];
    const float* angles = (const float*)d_in[1];
    if (n_in >= 2 && in_sizes[0] < in_sizes[1]) {
        const float* t = data; data = angles; angles = t;
    }
    int nA = (in_sizes[0] < in_sizes[1]) ? in_sizes[0] : in_sizes[1];

    float* out = (float*)d_out;

    dim3 pgrid(PW / 32, PW / 32);
    prep_kernel<<<pgrid, dim3(32, 8)>>>(data);

    dim3 rgrid(IMGW / 32, nA);
    radon_kernel<<<rgrid, 128>>>(angles, out);
}

// round 10
// speedup vs baseline: 1.1622x; 1.1622x over previous
#include <cuda_runtime.h>
#include <cuda_fp16.h>

typedef unsigned long long ull;

#define PW    768      // padded width/height
#define PAD   128      // border
#define IMGW  512
#define MAGIC 8388608.0f      // 2^23
#define MAGICH 8388607.5f     // 2^23 - 0.5

// fp16 differential quad images, 4x4 BLOCK-TILED:
//   element E(r,c) = (r>>2)*(PW*4) + (c<<2) + (r&3)
//   byte offset   = r*8 + c*32 + (r>>2)*24544   (identity, max 4.72MB -> fits u32)
// Texel = (v00, dx | dy, dxy); bilinear: val = (v00 + wr*dy) + wc*(dx + wr*dxy)
// A (normal): rows = image y, cols = image x.  B (transposed): rows = x, cols = y.
__device__ ull g_quadA[PW * PW];
__device__ ull g_quadB[PW * PW];

__device__ __forceinline__ int tile_idx(int r, int c) {
    return (r >> 2) * (PW * 4) + (c << 2) + (r & 3);
}

// ---------------- packed f32x2 helpers ----------------
__device__ __forceinline__ ull f2u(float a, float b) {
    ull r; asm("mov.b64 %0, {%1, %2};" : "=l"(r) : "f"(a), "f"(b)); return r;
}
__device__ __forceinline__ void u2f(ull v, float& a, float& b) {
    asm("mov.b64 {%0, %1}, %2;" : "=f"(a), "=f"(b) : "l"(v));
}
__device__ __forceinline__ ull fma2(ull a, ull b, ull c) {
    ull d; asm("fma.rn.f32x2 %0, %1, %2, %3;" : "=l"(d) : "l"(a), "l"(b), "l"(c)); return d;
}
__device__ __forceinline__ ull add2(ull a, ull b) {
    ull d; asm("add.rn.f32x2 %0, %1, %2;" : "=l"(d) : "l"(a), "l"(b)); return d;
}
__device__ __forceinline__ ull packq(float v00, float v01, float v10, float v11) {
    float dx  = v01 - v00;
    float dy  = v10 - v00;
    float dxy = (v11 - v10) - (v01 - v00);
    __half2 lo = __floats2half2_rn(v00, dx);
    __half2 hi = __floats2half2_rn(dy, dxy);
    unsigned a = *reinterpret_cast<unsigned*>(&lo);
    unsigned b = *reinterpret_cast<unsigned*>(&hi);
    return (ull)a | ((ull)b << 32);
}

__device__ __forceinline__ float ipad(const float* img, int v, int u) {
    int sv = v - PAD, su = u - PAD;
    if (sv < 0 || sv >= IMGW || su < 0 || su >= IMGW) return 0.0f;
    return __ldg(&img[sv * IMGW + su]);
}

// ---------------- fused prep: both differential quad images (tiled) ----------------
__global__ void prep_kernel(const float* __restrict__ img) {
    __shared__ float S[33][34];            // S[j][i] = Ip(r0+j, c0+i)
    const int r0 = blockIdx.x * 32;
    const int c0 = blockIdx.y * 32;
    const int tx = threadIdx.x;            // 0..31
    const int ty = threadIdx.y;            // 0..7

    for (int j = ty; j < 33; j += 8)
        for (int i = tx; i < 33; i += 32)
            S[j][i] = ipad(img, r0 + j, c0 + i);
    __syncthreads();

    for (int j = ty; j < 32; j += 8) {
        g_quadA[tile_idx(r0 + j, c0 + tx)] =
            packq(S[j][tx], S[j][tx + 1], S[j + 1][tx], S[j + 1][tx + 1]);
        g_quadB[tile_idx(c0 + j, r0 + tx)] =
            packq(S[tx][j], S[tx + 1][j], S[tx][j + 1], S[tx + 1][j + 1]);
    }
}

// ---------------- radon helpers ----------------
// Magic-floor coord gen: from packed (col,row) produce weights + 32-bit tiled offset.
// Biased ints Ri = B + r, Ci = B + c (B = 0x4B000000, B%4==0). All bias terms
// cancel through KOFF in wrapping u32; true offset < 2^32 so the result is exact.
__device__ __forceinline__ ull cgen(ull p, ull MAGH2, ull NMAG2, ull NEG1,
                                    unsigned KOFF, unsigned& off) {
    ull t = add2(p, MAGH2);            // MAGIC + floor(col|row)
    ull f = add2(t, NMAG2);            // exact floors as floats
    ull w = fma2(f, NEG1, p);          // fractional weights (wc, wr)
    float tcf, trf; u2f(t, tcf, trf);
    unsigned Ci = (unsigned)__float_as_int(tcf);
    int      Ri = __float_as_int(trf);
    off = (unsigned)Ri * 8u + Ci * 32u + (unsigned)(Ri >> 2) * 24544u + KOFF;
    return w;
}

__device__ __forceinline__ void consume(uint2 q, ull w, float& acc) {
    __half2 A = *reinterpret_cast<__half2*>(&q.x);   // (v00, dx)
    __half2 B = *reinterpret_cast<__half2*>(&q.y);   // (dy, dxy)
    float wc, wr; u2f(w, wc, wr);
    unsigned wr2u;
    asm("cvt.rn.f16x2.f32 %0, %1, %2;" : "=r"(wr2u) : "f"(wr), "f"(wr));
    __half2 wr2 = *reinterpret_cast<__half2*>(&wr2u);
    __half2 mh = __hfma2(wr2, B, A);                 // (m0, md)
    acc += __low2float(mh);
    acc = fmaf(wc, __high2float(mh), acc);
}

// ---------------- main radon kernel ----------------
// Persistent grid-stride over tiles (tile = angle*16 + xchunk).
// Warp = 8 detectors x 4 y-lanes; 2 y-streams; explicit 4-sample load batching.
__global__ void __launch_bounds__(128, 12) radon_kernel(const float* __restrict__ angles,
                                                        float* __restrict__ out,
                                                        int nTiles) {
    const int lane = threadIdx.x & 31;
    const int warp = threadIdx.x >> 5;
    const int xi   = lane & 7;
    const int yi   = lane >> 3;

    constexpr unsigned BI   = 0x4B000000u;
    constexpr unsigned KOFF = 0u - (BI * 40u + (BI >> 2) * 24544u);

    const ull NEG1  = f2u(-1.0f, -1.0f);
    const ull ONE2  = f2u(1.0f, 1.0f);
    const ull MAGH2 = f2u(MAGICH, MAGICH);
    const ull NMAG2 = f2u(-MAGIC, -MAGIC);

    for (int tile = blockIdx.x; tile < nTiles; tile += gridDim.x) {
        const int a  = tile >> 4;
        const int xc = tile & 15;
        const int x  = xc * 32 + warp * 8 + xi;

        float s, c;
        sincosf(__ldg(&angles[a]), &s, &c);

        const float bx = fmaf((float)x, 2.0f / 512.0f, 1.0f / 512.0f - 1.0f);
        const float Cx = fmaf(256.0f * c, bx, 383.5f - 255.5f * s);
        const float Cy = fmaf(-256.0f * s, bx, 383.5f - 255.5f * c);

        const bool  tr   = fabsf(s) > fabsf(c);
        const float dcol = tr ? c : s;
        const float drow = tr ? s : c;
        const float Ca   = tr ? Cy : Cx;
        const float Cb   = tr ? Cx : Cy;
        const char* gq   = (const char*)(tr ? g_quadB : g_quadA);

        const ull S4 = f2u(4.0f * dcol, 4.0f * drow);
        const float y0 = (float)yi;
        ull C0 = f2u(fmaf(y0,          dcol, Ca), fmaf(y0,          drow, Cb));
        ull C1 = f2u(fmaf(y0 + 256.0f, dcol, Ca), fmaf(y0 + 256.0f, drow, Cb));

        float acc0 = 0.0f, acc1 = 0.0f;
        ull t2 = f2u(0.0f, 0.0f);

        #pragma unroll 1
        for (int i = 0; i < 64; i += 2) {
            // ---- coord gen for 4 samples: streams {0,1} x steps {t, t+1} ----
            ull tb = add2(t2, ONE2);
            ull p0 = fma2(t2, S4, C0);
            ull p1 = fma2(t2, S4, C1);
            ull p2 = fma2(tb, S4, C0);
            ull p3 = fma2(tb, S4, C1);
            unsigned o0, o1, o2, o3;
            ull w0 = cgen(p0, MAGH2, NMAG2, NEG1, KOFF, o0);
            ull w1 = cgen(p1, MAGH2, NMAG2, NEG1, KOFF, o1);
            ull w2 = cgen(p2, MAGH2, NMAG2, NEG1, KOFF, o2);
            ull w3 = cgen(p3, MAGH2, NMAG2, NEG1, KOFF, o3);

            // ---- 4 loads issued back-to-back (MLP = 4) ----
            uint2 q0 = __ldg(reinterpret_cast<const uint2*>(gq + o0));
            uint2 q1 = __ldg(reinterpret_cast<const uint2*>(gq + o1));
            uint2 q2 = __ldg(reinterpret_cast<const uint2*>(gq + o2));
            uint2 q3 = __ldg(reinterpret_cast<const uint2*>(gq + o3));

            // ---- consume ----
            consume(q0, w0, acc0);
            consume(q1, w1, acc1);
            consume(q2, w2, acc0);
            consume(q3, w3, acc1);

            t2 = add2(tb, ONE2);
        }

        float v = acc0 + acc1;
        v += __shfl_xor_sync(0xFFFFFFFFu, v, 8);
        v += __shfl_xor_sync(0xFFFFFFFFu, v, 16);
        if (yi == 0)
            out[a * IMGW + x] = v;
    }
}

extern "C" void kernel_launch(void* const* d_in, const int* in_sizes, int n_in,
                              void* d_out, int out_size) {
    const float* data   = (const float*)d_in[0];
    const float* angles = (const float*)d_in[1];
    if (n_in >= 2 && in_sizes[0] < in_sizes[1]) {
        const float* t = data; data = angles; angles = t;
    }
    int nA = (in_sizes[0] < in_sizes[1]) ? in_sizes[0] : in_sizes[1];

    float* out = (float*)d_out;

    dim3 pgrid(PW / 32, PW / 32);
    prep_kernel<<<pgrid, dim3(32, 8)>>>(data);

    int nTiles = nA * (IMGW / 32);
    int grid = 152 * 12;               // persistent: 12 blocks per SM on GB300
    if (grid > nTiles) grid = nTiles;
    radon_kernel<<<grid, 128>>>(angles, out, nTiles);
}